// round 13
// baseline (speedup 1.0000x reference)
#include <cuda_runtime.h>
#include <math.h>

// Problem constants (fixed by the dataset)
#define NB        8          // batch
#define C_IN      4
#define N_ETYPE   5
#define N_NTYPE   7
#define C_OUT     32
#define TEMB_CH   512
#define FAN       55         // N_ETYPE * (C_IN + N_NTYPE)
#define NMAX      400000

// Scatter accumulators (zero at load; gemv re-zeros what it consumes):
__device__ float    g_xsum[NMAX * N_ETYPE * 4];   // 32 MB
__device__ unsigned g_cnt [NMAX * N_ETYPE * 2];   // 16 MB
__device__ float    g_l2  [NB * TEMB_CH];         // lin2 pre-activation accum
__device__ float    g_inj [NB * C_OUT];
__device__ int      g_done0;                      // temb-block arrivals
__device__ int      g_done1;                      // inj-block arrivals

// ---------------------------------------------------------------------------
// MEGA kernel, 512 threads/block:
//  blocks [0,64)   : temb lin1+lin2 partials -> g_l2 (atomicAdd), signal done0
//  blocks [64,72)  : spin on done0==64, then inj = swish(l2+b2) @ Wt -> g_inj,
//                    re-zero g_l2, self-reset counters for graph replay
//  blocks [72,...) : edge scatter, 2 edges/thread, direct x/ntype gather
// Safe: blocks 0-63 are scheduled in wave 1 before blocks 64-71, so the spin
// cannot deadlock.
// ---------------------------------------------------------------------------
__global__ void __launch_bounds__(512)
mega_kernel(const float* __restrict__ t,
            const float* __restrict__ W1,
            const float* __restrict__ b1,
            const float* __restrict__ W2,
            const float* __restrict__ b2,
            const float* __restrict__ Wt,
            const int* __restrict__ ei,
            const int* __restrict__ etype,
            const int* __restrict__ ntype,
            const float* __restrict__ x,
            int E) {
    const int tid = threadIdx.x;

    if (blockIdx.x < 64) {
        // ---- temb: (kseg, col_tile) computes lin1+lin2 for all 8 batches ----
        __shared__ float emb[NB][128];
        __shared__ float h1s[NB][64];
        const int ks = blockIdx.x >> 3;
        const int bo = blockIdx.x & 7;
        const int b  = tid >> 6;
        const int j  = tid & 63;

        {
            float f = expf(-(float)j * (logf(10000.0f) / 63.0f));
            float ang = t[b] * f;
            emb[b][j]      = sinf(ang);
            emb[b][j + 64] = cosf(ang);
        }
        __syncthreads();
        {
            float s = b1[ks * 64 + j];
            const float* w = W1 + ks * 64 + j;
            #pragma unroll 8
            for (int i = 0; i < 128; i++) s += emb[b][i] * w[(size_t)i * TEMB_CH];
            h1s[b][j] = s * (1.0f / (1.0f + expf(-s)));
        }
        __syncthreads();
        {
            float s = 0.0f;
            const float* w = W2 + (size_t)(ks * 64) * TEMB_CH + bo * 64 + j;
            #pragma unroll 8
            for (int k = 0; k < 64; k++) s += h1s[b][k] * w[(size_t)k * TEMB_CH];
            atomicAdd(g_l2 + b * TEMB_CH + bo * 64 + j, s);
        }
        __syncthreads();
        if (tid == 0) {
            __threadfence();
            atomicAdd(&g_done0, 1);
        }
        return;
    }

    if (blockIdx.x < 72) {
        // ---- inj: wait for all temb partials, then project to node channels ----
        __shared__ float sws[TEMB_CH];
        __shared__ float part[16][33];
        const int b = blockIdx.x - 64;

        if (tid == 0) {
            while (atomicAdd(&g_done0, 0) < 64) __nanosleep(200);
            __threadfence();
        }
        __syncthreads();

        for (int i = tid; i < TEMB_CH; i += 512) {
            float v = __ldcg(g_l2 + b * TEMB_CH + i) + b2[i];
            sws[i] = v * (1.0f / (1.0f + expf(-v)));
        }
        __syncthreads();
        for (int i = tid; i < TEMB_CH; i += 512)   // restore zero-invariant
            g_l2[b * TEMB_CH + i] = 0.0f;

        const int c  = tid & 31;
        const int ks = tid >> 5;                   // 0..15
        const float* sw = sws + ks * 32;
        const float* w  = Wt + (ks * 32) * C_OUT + c;
        float s = 0.0f;
        #pragma unroll 8
        for (int i = 0; i < 32; i++) s += sw[i] * w[i * C_OUT];
        part[ks][c] = s;
        __syncthreads();

        if (tid < 32) {
            float v = 0.0f;
            #pragma unroll
            for (int k = 0; k < 16; k++) v += part[k][tid];
            g_inj[b * C_OUT + tid] = v;
        }
        __syncthreads();
        if (tid == 0) {
            __threadfence();
            int r = atomicAdd(&g_done1, 1);
            if (r == 7) {                 // last inj block resets both counters
                atomicExch(&g_done0, 0);
                atomicExch(&g_done1, 0);
            }
        }
        return;
    }

    // ---- edge scatter: 2 edges per thread. Edge streams are read-once ->
    // streaming loads (evict-first) to keep agg buckets L2-resident. ----
    int e2 = ((blockIdx.x - 72) * blockDim.x + tid) * 2;
    if (e2 >= E) return;
    int2 rows = __ldcs(reinterpret_cast<const int2*>(ei + e2));
    int2 cols = __ldcs(reinterpret_cast<const int2*>(ei + E + e2));
    int2 ets  = __ldcs(reinterpret_cast<const int2*>(etype + e2));

    int nt0 = __ldg(ntype + cols.x);
    int nt1 = __ldg(ntype + cols.y);
    float4 xv0 = *reinterpret_cast<const float4*>(x + (size_t)cols.x * C_IN);
    float4 xv1 = *reinterpret_cast<const float4*>(x + (size_t)cols.y * C_IN);

    size_t bk0 = (size_t)rows.x * N_ETYPE + ets.x;
    size_t bk1 = (size_t)rows.y * N_ETYPE + ets.y;

    asm volatile("red.global.add.v4.f32 [%0], {%1,%2,%3,%4};"
                 :: "l"(g_xsum + bk0 * 4), "f"(xv0.x), "f"(xv0.y), "f"(xv0.z), "f"(xv0.w)
                 : "memory");
    asm volatile("red.global.add.v4.f32 [%0], {%1,%2,%3,%4};"
                 :: "l"(g_xsum + bk1 * 4), "f"(xv1.x), "f"(xv1.y), "f"(xv1.z), "f"(xv1.w)
                 : "memory");
    atomicAdd(g_cnt + bk0 * 2 + (nt0 >> 2), 1u << ((nt0 & 3) * 8));
    atomicAdd(g_cnt + bk1 * 2 + (nt1 >> 2), 1u << ((nt1 & 3) * 8));
}

// ---------------------------------------------------------------------------
// u8 counter -> exact fp32 via PRMT magic number (no I2F, no mask chains).
// ---------------------------------------------------------------------------
template <int K>
__device__ __forceinline__ float byte2f(unsigned w) {
    unsigned r;
    asm("prmt.b32 %0, %1, %2, %3;"
        : "=r"(r) : "r"(w), "r"(0x4B000000u), "n"(0x7540u | K));
    return __uint_as_float(r) - 8388608.0f;
}

// ---------------------------------------------------------------------------
// Per-node GEMV v6 (best measured ~53us): 2 full nodes per thread; weights as
// ulonglong2 from smem (one LDS.128 = two ready FFMA2 operands); counters
// pre-loaded with uint4 (n0 even -> 80B stride, 16B aligned); xsum loaded
// per-et inside the loop; PRMT count conversion; 128 threads, 5 blocks/SM.
// ---------------------------------------------------------------------------
__global__ void __launch_bounds__(128, 5)
gemv_kernel(const float* __restrict__ Wc,
            const int* __restrict__ batch_id,
            float* __restrict__ out,
            int N) {
    __shared__ __align__(16) float Ws[FAN * C_OUT];   // pre-scaled by 0.2
    __shared__ float injs[NB * 33];
    const int tid = threadIdx.x;
    for (int i = tid; i < FAN * C_OUT; i += blockDim.x) Ws[i] = Wc[i] * 0.2f;
    for (int i = tid; i < NB * C_OUT; i += blockDim.x) {
        int b = i >> 5, c = i & 31;
        injs[b * 33 + c] = g_inj[i];
    }
    __syncthreads();

    int n0 = (blockIdx.x * blockDim.x + tid) * 2;
    if (n0 >= N) return;

    unsigned long long acc0[16], acc1[16];
    #pragma unroll
    for (int k = 0; k < 16; k++) { acc0[k] = 0ULL; acc1[k] = 0ULL; }

    float*    xp = g_xsum + (size_t)n0 * (N_ETYPE * 4);   // 16B aligned
    unsigned* cp = g_cnt  + (size_t)n0 * (N_ETYPE * 2);   // 16B aligned (n0 even)

    // Both nodes' counters: 5 x LDG.128 (20 words contiguous).
    unsigned cA[10], cB[10];
    {
        uint4 a0 = *reinterpret_cast<uint4*>(cp);
        uint4 a1 = *reinterpret_cast<uint4*>(cp + 4);
        uint4 a2 = *reinterpret_cast<uint4*>(cp + 8);
        uint4 a3 = *reinterpret_cast<uint4*>(cp + 12);
        uint4 a4 = *reinterpret_cast<uint4*>(cp + 16);
        cA[0]=a0.x; cA[1]=a0.y; cA[2]=a0.z; cA[3]=a0.w;
        cA[4]=a1.x; cA[5]=a1.y; cA[6]=a1.z; cA[7]=a1.w;
        cA[8]=a2.x; cA[9]=a2.y;
        cB[0]=a2.z; cB[1]=a2.w;
        cB[2]=a3.x; cB[3]=a3.y; cB[4]=a3.z; cB[5]=a3.w;
        cB[6]=a4.x; cB[7]=a4.y; cB[8]=a4.z; cB[9]=a4.w;
    }

    #pragma unroll
    for (int et = 0; et < N_ETYPE; et++) {
        float4 v0 = *reinterpret_cast<float4*>(xp + et * 4);
        float4 v1 = *reinterpret_cast<float4*>(xp + N_ETYPE * 4 + et * 4);
        unsigned lo0 = cA[et * 2], hi0 = cA[et * 2 + 1];
        unsigned lo1 = cB[et * 2], hi1 = cB[et * 2 + 1];
        float a0[11], a1[11];
        a0[0] = v0.x; a0[1] = v0.y; a0[2] = v0.z; a0[3] = v0.w;
        a0[4] = byte2f<0>(lo0); a0[5] = byte2f<1>(lo0);
        a0[6] = byte2f<2>(lo0); a0[7] = byte2f<3>(lo0);
        a0[8] = byte2f<0>(hi0); a0[9] = byte2f<1>(hi0);
        a0[10] = byte2f<2>(hi0);
        a1[0] = v1.x; a1[1] = v1.y; a1[2] = v1.z; a1[3] = v1.w;
        a1[4] = byte2f<0>(lo1); a1[5] = byte2f<1>(lo1);
        a1[6] = byte2f<2>(lo1); a1[7] = byte2f<3>(lo1);
        a1[8] = byte2f<0>(hi1); a1[9] = byte2f<1>(hi1);
        a1[10] = byte2f<2>(hi1);

        #pragma unroll
        for (int j = 0; j < 11; j++) {
            const ulonglong2* Wv =
                reinterpret_cast<const ulonglong2*>(&Ws[(et * 11 + j) * C_OUT]);
            unsigned long long av0, av1;
            asm("mov.b64 %0, {%1, %1};" : "=l"(av0) : "f"(a0[j]));
            asm("mov.b64 %0, {%1, %1};" : "=l"(av1) : "f"(a1[j]));
            #pragma unroll
            for (int q = 0; q < 8; q++) {
                ulonglong2 w = Wv[q];               // one LDS.128, two u64 operands
                asm("fma.rn.f32x2 %0, %1, %2, %0;"
                    : "+l"(acc0[2 * q + 0]) : "l"(av0), "l"(w.x));
                asm("fma.rn.f32x2 %0, %1, %2, %0;"
                    : "+l"(acc0[2 * q + 1]) : "l"(av0), "l"(w.y));
                asm("fma.rn.f32x2 %0, %1, %2, %0;"
                    : "+l"(acc1[2 * q + 0]) : "l"(av1), "l"(w.x));
                asm("fma.rn.f32x2 %0, %1, %2, %0;"
                    : "+l"(acc1[2 * q + 1]) : "l"(av1), "l"(w.y));
            }
        }
    }

    int2 bb = *reinterpret_cast<const int2*>(batch_id + n0);
    const float* iv0 = &injs[bb.x * 33];
    const float* iv1 = &injs[bb.y * 33];
    float* op0 = out + (size_t)n0 * C_OUT;
    float* op1 = op0 + C_OUT;
    #pragma unroll
    for (int k = 0; k < 16; k += 2) {
        float l0, h0, l1, h1;
        asm("mov.b64 {%0, %1}, %2;" : "=f"(l0), "=f"(h0) : "l"(acc0[k]));
        asm("mov.b64 {%0, %1}, %2;" : "=f"(l1), "=f"(h1) : "l"(acc0[k + 1]));
        float4 o; o.x = l0 + iv0[2*k]; o.y = h0 + iv0[2*k+1];
        o.z = l1 + iv0[2*k+2]; o.w = h1 + iv0[2*k+3];
        *reinterpret_cast<float4*>(op0 + 2 * k) = o;
        asm("mov.b64 {%0, %1}, %2;" : "=f"(l0), "=f"(h0) : "l"(acc1[k]));
        asm("mov.b64 {%0, %1}, %2;" : "=f"(l1), "=f"(h1) : "l"(acc1[k + 1]));
        float4 p; p.x = l0 + iv1[2*k]; p.y = h0 + iv1[2*k+1];
        p.z = l1 + iv1[2*k+2]; p.w = h1 + iv1[2*k+3];
        *reinterpret_cast<float4*>(op1 + 2 * k) = p;
    }

    // Re-zero both nodes' accumulators.
    float4 z4 = make_float4(0.f, 0.f, 0.f, 0.f);
    #pragma unroll
    for (int i = 0; i < 2 * N_ETYPE; i++)
        *reinterpret_cast<float4*>(xp + i * 4) = z4;
    uint4 zu = make_uint4(0u, 0u, 0u, 0u);
    #pragma unroll
    for (int i = 0; i < 5; i++)
        *reinterpret_cast<uint4*>(cp + i * 4) = zu;
}

// ---------------------------------------------------------------------------
// Inputs (metadata order):
//  0 x [N,4] f32        1 t [8] f32          2 edge_index [2,E] i32
//  3 edge_type [E] i32  4 node_type [N] i32  5 batch_id [N] i32
//  6 W_conv [55,32] f32 7 W1 [128,512]       8 b1 [512]
//  9 W2 [512,512]      10 b2 [512]          11 W_temb [512,32]
// Output: [N,32] f32
// ---------------------------------------------------------------------------
extern "C" void kernel_launch(void* const* d_in, const int* in_sizes, int n_in,
                              void* d_out, int out_size) {
    const float* x        = (const float*)d_in[0];
    const float* t        = (const float*)d_in[1];
    const int*   ei       = (const int*)d_in[2];
    const int*   etype    = (const int*)d_in[3];
    const int*   ntype    = (const int*)d_in[4];
    const int*   batch_id = (const int*)d_in[5];
    const float* W_conv   = (const float*)d_in[6];
    const float* W1       = (const float*)d_in[7];
    const float* b1       = (const float*)d_in[8];
    const float* W2       = (const float*)d_in[9];
    const float* b2       = (const float*)d_in[10];
    const float* W_temb   = (const float*)d_in[11];
    float* out = (float*)d_out;

    const int E = in_sizes[3];
    const int N = in_sizes[4];
    const int edge_blocks = (E / 2 + 511) / 512;

    mega_kernel<<<72 + edge_blocks, 512>>>(t, W1, b1, W2, b2, W_temb,
                                           ei, etype, ntype, x, E);
    gemv_kernel<<<(N / 2 + 127) / 128, 128>>>(W_conv, batch_id, out, N);
}

// round 14
// speedup vs baseline: 1.0319x; 1.0319x over previous
#include <cuda_runtime.h>
#include <math.h>

// Problem constants (fixed by the dataset)
#define NB        8          // batch
#define C_IN      4
#define N_ETYPE   5
#define N_NTYPE   7
#define C_OUT     32
#define TEMB_CH   512
#define FAN       55         // N_ETYPE * (C_IN + N_NTYPE)
#define NMAX      400000

// Scatter accumulators (zero at load; gemv re-zeros what it consumes):
__device__ float    g_xsum[NMAX * N_ETYPE * 4];   // 32 MB
__device__ unsigned g_cnt [NMAX * N_ETYPE * 2];   // 16 MB
__device__ float    g_l2  [NB * TEMB_CH];         // lin2 pre-activation accum
__device__ float    g_inj [NB * C_OUT];
__device__ int      g_done0;                      // temb-block arrivals
__device__ int      g_done1;                      // inj-block arrivals

// ---------------------------------------------------------------------------
// MEGA kernel (R12-proven form), 512 threads/block:
//  blocks [0,64)   : temb lin1+lin2 partials -> g_l2 (atomicAdd), signal done0
//  blocks [64,72)  : spin on done0==64, then inj = swish(l2+b2) @ Wt -> g_inj,
//                    re-zero g_l2, self-reset counters for graph replay
//  blocks [72,...) : edge scatter, 2 edges/thread, direct x/ntype gather
// ---------------------------------------------------------------------------
__global__ void __launch_bounds__(512)
mega_kernel(const float* __restrict__ t,
            const float* __restrict__ W1,
            const float* __restrict__ b1,
            const float* __restrict__ W2,
            const float* __restrict__ b2,
            const float* __restrict__ Wt,
            const int* __restrict__ ei,
            const int* __restrict__ etype,
            const int* __restrict__ ntype,
            const float* __restrict__ x,
            int E) {
    const int tid = threadIdx.x;

    if (blockIdx.x < 64) {
        __shared__ float emb[NB][128];
        __shared__ float h1s[NB][64];
        const int ks = blockIdx.x >> 3;
        const int bo = blockIdx.x & 7;
        const int b  = tid >> 6;
        const int j  = tid & 63;

        {
            float f = expf(-(float)j * (logf(10000.0f) / 63.0f));
            float ang = t[b] * f;
            emb[b][j]      = sinf(ang);
            emb[b][j + 64] = cosf(ang);
        }
        __syncthreads();
        {
            float s = b1[ks * 64 + j];
            const float* w = W1 + ks * 64 + j;
            #pragma unroll 8
            for (int i = 0; i < 128; i++) s += emb[b][i] * w[(size_t)i * TEMB_CH];
            h1s[b][j] = s * (1.0f / (1.0f + expf(-s)));
        }
        __syncthreads();
        {
            float s = 0.0f;
            const float* w = W2 + (size_t)(ks * 64) * TEMB_CH + bo * 64 + j;
            #pragma unroll 8
            for (int k = 0; k < 64; k++) s += h1s[b][k] * w[(size_t)k * TEMB_CH];
            atomicAdd(g_l2 + b * TEMB_CH + bo * 64 + j, s);
        }
        __syncthreads();
        if (tid == 0) {
            __threadfence();
            atomicAdd(&g_done0, 1);
        }
        return;
    }

    if (blockIdx.x < 72) {
        __shared__ float sws[TEMB_CH];
        __shared__ float part[16][33];
        const int b = blockIdx.x - 64;

        if (tid == 0) {
            while (atomicAdd(&g_done0, 0) < 64) __nanosleep(200);
            __threadfence();
        }
        __syncthreads();

        for (int i = tid; i < TEMB_CH; i += 512) {
            float v = __ldcg(g_l2 + b * TEMB_CH + i) + b2[i];
            sws[i] = v * (1.0f / (1.0f + expf(-v)));
        }
        __syncthreads();
        for (int i = tid; i < TEMB_CH; i += 512)   // restore zero-invariant
            g_l2[b * TEMB_CH + i] = 0.0f;

        const int c  = tid & 31;
        const int ks = tid >> 5;                   // 0..15
        const float* sw = sws + ks * 32;
        const float* w  = Wt + (ks * 32) * C_OUT + c;
        float s = 0.0f;
        #pragma unroll 8
        for (int i = 0; i < 32; i++) s += sw[i] * w[i * C_OUT];
        part[ks][c] = s;
        __syncthreads();

        if (tid < 32) {
            float v = 0.0f;
            #pragma unroll
            for (int k = 0; k < 16; k++) v += part[k][tid];
            g_inj[b * C_OUT + tid] = v;
        }
        __syncthreads();
        if (tid == 0) {
            __threadfence();
            int r = atomicAdd(&g_done1, 1);
            if (r == 7) {
                atomicExch(&g_done0, 0);
                atomicExch(&g_done1, 0);
            }
        }
        return;
    }

    // ---- edge scatter: 2 edges per thread (default cache policy) ----
    int e2 = ((blockIdx.x - 72) * blockDim.x + tid) * 2;
    if (e2 >= E) return;
    int2 rows = *reinterpret_cast<const int2*>(ei + e2);
    int2 cols = *reinterpret_cast<const int2*>(ei + E + e2);
    int2 ets  = *reinterpret_cast<const int2*>(etype + e2);

    int nt0 = __ldg(ntype + cols.x);
    int nt1 = __ldg(ntype + cols.y);
    float4 xv0 = *reinterpret_cast<const float4*>(x + (size_t)cols.x * C_IN);
    float4 xv1 = *reinterpret_cast<const float4*>(x + (size_t)cols.y * C_IN);

    size_t bk0 = (size_t)rows.x * N_ETYPE + ets.x;
    size_t bk1 = (size_t)rows.y * N_ETYPE + ets.y;

    asm volatile("red.global.add.v4.f32 [%0], {%1,%2,%3,%4};"
                 :: "l"(g_xsum + bk0 * 4), "f"(xv0.x), "f"(xv0.y), "f"(xv0.z), "f"(xv0.w)
                 : "memory");
    asm volatile("red.global.add.v4.f32 [%0], {%1,%2,%3,%4};"
                 :: "l"(g_xsum + bk1 * 4), "f"(xv1.x), "f"(xv1.y), "f"(xv1.z), "f"(xv1.w)
                 : "memory");
    atomicAdd(g_cnt + bk0 * 2 + (nt0 >> 2), 1u << ((nt0 & 3) * 8));
    atomicAdd(g_cnt + bk1 * 2 + (nt1 >> 2), 1u << ((nt1 & 3) * 8));
}

// ---------------------------------------------------------------------------
// u8 counter -> exact fp32 via PRMT magic number.
// ---------------------------------------------------------------------------
template <int K>
__device__ __forceinline__ float byte2f(unsigned w) {
    unsigned r;
    asm("prmt.b32 %0, %1, %2, %3;"
        : "=r"(r) : "r"(w), "r"(0x4B000000u), "n"(0x7540u | K));
    return __uint_as_float(r) - 8388608.0f;
}

// ---------------------------------------------------------------------------
// GEMV v9: 4 nodes x 16 channels per thread. Even/odd threads take channel
// halves [0,16)/[16,32); a thread-pair covers 4 nodes; a warp covers 64 nodes
// with only 4 warp-level LDS.128 per j => 3.44 LDS/node (half of v6), the two
// halves hitting disjoint smem banks 0-15/16-31 (conflict-free broadcast).
// ---------------------------------------------------------------------------
__global__ void __launch_bounds__(128, 3)
gemv_kernel(const float* __restrict__ Wc,
            const int* __restrict__ batch_id,
            float* __restrict__ out,
            int N) {
    __shared__ __align__(16) float Ws[FAN * C_OUT];   // pre-scaled by 0.2
    __shared__ float injs[NB * 33];
    const int tid = threadIdx.x;
    for (int i = tid; i < FAN * C_OUT; i += blockDim.x) Ws[i] = Wc[i] * 0.2f;
    for (int i = tid; i < NB * C_OUT; i += blockDim.x) {
        int b = i >> 5, c = i & 31;
        injs[b * 33 + c] = g_inj[i];
    }
    __syncthreads();

    const int gid  = blockIdx.x * blockDim.x + tid;
    const int h    = gid & 1;                 // channel half
    const int base = (gid >> 1) * 4;          // first of this pair's 4 nodes
    if (base >= N) return;

    unsigned long long acc[4][8];
    #pragma unroll
    for (int nd = 0; nd < 4; nd++)
        #pragma unroll
        for (int k = 0; k < 8; k++) acc[nd][k] = 0ULL;

    float*    xp = g_xsum + (size_t)base * (N_ETYPE * 4);   // 16B aligned
    unsigned* cp = g_cnt  + (size_t)base * (N_ETYPE * 2);   // 16B aligned (base%4==0)

    #pragma unroll
    for (int et = 0; et < N_ETYPE; et++) {
        float a[4][11];
        #pragma unroll
        for (int nd = 0; nd < 4; nd++) {
            float4 v  = *reinterpret_cast<float4*>(xp + nd * (N_ETYPE * 4) + et * 4);
            uint2  c  = *reinterpret_cast<uint2*>(cp + nd * (N_ETYPE * 2) + et * 2);
            a[nd][0] = v.x; a[nd][1] = v.y; a[nd][2] = v.z; a[nd][3] = v.w;
            a[nd][4] = byte2f<0>(c.x); a[nd][5] = byte2f<1>(c.x);
            a[nd][6] = byte2f<2>(c.x); a[nd][7] = byte2f<3>(c.x);
            a[nd][8] = byte2f<0>(c.y); a[nd][9] = byte2f<1>(c.y);
            a[nd][10] = byte2f<2>(c.y);
        }

        #pragma unroll
        for (int j = 0; j < 11; j++) {
            const ulonglong2* Wv =
                reinterpret_cast<const ulonglong2*>(&Ws[(et * 11 + j) * C_OUT + h * 16]);
            ulonglong2 w0 = Wv[0];
            ulonglong2 w1 = Wv[1];
            ulonglong2 w2 = Wv[2];
            ulonglong2 w3 = Wv[3];
            #pragma unroll
            for (int nd = 0; nd < 4; nd++) {
                unsigned long long av;
                asm("mov.b64 %0, {%1, %1};" : "=l"(av) : "f"(a[nd][j]));
                asm("fma.rn.f32x2 %0, %1, %2, %0;" : "+l"(acc[nd][0]) : "l"(av), "l"(w0.x));
                asm("fma.rn.f32x2 %0, %1, %2, %0;" : "+l"(acc[nd][1]) : "l"(av), "l"(w0.y));
                asm("fma.rn.f32x2 %0, %1, %2, %0;" : "+l"(acc[nd][2]) : "l"(av), "l"(w1.x));
                asm("fma.rn.f32x2 %0, %1, %2, %0;" : "+l"(acc[nd][3]) : "l"(av), "l"(w1.y));
                asm("fma.rn.f32x2 %0, %1, %2, %0;" : "+l"(acc[nd][4]) : "l"(av), "l"(w2.x));
                asm("fma.rn.f32x2 %0, %1, %2, %0;" : "+l"(acc[nd][5]) : "l"(av), "l"(w2.y));
                asm("fma.rn.f32x2 %0, %1, %2, %0;" : "+l"(acc[nd][6]) : "l"(av), "l"(w3.x));
                asm("fma.rn.f32x2 %0, %1, %2, %0;" : "+l"(acc[nd][7]) : "l"(av), "l"(w3.y));
            }
        }
    }

    int4 bb = *reinterpret_cast<const int4*>(batch_id + base);
    const int bbl[4] = {bb.x, bb.y, bb.z, bb.w};
    #pragma unroll
    for (int nd = 0; nd < 4; nd++) {
        const float* iv = &injs[bbl[nd] * 33 + h * 16];
        float* op = out + (size_t)(base + nd) * C_OUT + h * 16;
        #pragma unroll
        for (int k = 0; k < 8; k += 2) {
            float l0, h0, l1, h1;
            asm("mov.b64 {%0, %1}, %2;" : "=f"(l0), "=f"(h0) : "l"(acc[nd][k]));
            asm("mov.b64 {%0, %1}, %2;" : "=f"(l1), "=f"(h1) : "l"(acc[nd][k + 1]));
            float4 o;
            o.x = l0 + iv[2 * k + 0];
            o.y = h0 + iv[2 * k + 1];
            o.z = l1 + iv[2 * k + 2];
            o.w = h1 + iv[2 * k + 3];
            *reinterpret_cast<float4*>(op + 2 * k) = o;
        }
    }

    // Re-zero: h==0 clears nodes base..base+1, h==1 clears base+2..base+3.
    {
        float*    zxp = xp + h * 2 * (N_ETYPE * 4);   // +40 floats: 16B aligned
        unsigned* zcp = cp + h * 2 * (N_ETYPE * 2);   // +20 words : 16B aligned
        float4 z4 = make_float4(0.f, 0.f, 0.f, 0.f);
        #pragma unroll
        for (int i = 0; i < 10; i++)
            *reinterpret_cast<float4*>(zxp + i * 4) = z4;
        uint4 zu = make_uint4(0u, 0u, 0u, 0u);
        #pragma unroll
        for (int i = 0; i < 5; i++)
            *reinterpret_cast<uint4*>(zcp + i * 4) = zu;
    }
}

// ---------------------------------------------------------------------------
// Inputs (metadata order):
//  0 x [N,4] f32        1 t [8] f32          2 edge_index [2,E] i32
//  3 edge_type [E] i32  4 node_type [N] i32  5 batch_id [N] i32
//  6 W_conv [55,32] f32 7 W1 [128,512]       8 b1 [512]
//  9 W2 [512,512]      10 b2 [512]          11 W_temb [512,32]
// Output: [N,32] f32
// ---------------------------------------------------------------------------
extern "C" void kernel_launch(void* const* d_in, const int* in_sizes, int n_in,
                              void* d_out, int out_size) {
    const float* x        = (const float*)d_in[0];
    const float* t        = (const float*)d_in[1];
    const int*   ei       = (const int*)d_in[2];
    const int*   etype    = (const int*)d_in[3];
    const int*   ntype    = (const int*)d_in[4];
    const int*   batch_id = (const int*)d_in[5];
    const float* W_conv   = (const float*)d_in[6];
    const float* W1       = (const float*)d_in[7];
    const float* b1       = (const float*)d_in[8];
    const float* W2       = (const float*)d_in[9];
    const float* b2       = (const float*)d_in[10];
    const float* W_temb   = (const float*)d_in[11];
    float* out = (float*)d_out;

    const int E = in_sizes[3];
    const int N = in_sizes[4];
    const int edge_blocks = (E / 2 + 511) / 512;

    mega_kernel<<<72 + edge_blocks, 512>>>(t, W1, b1, W2, b2, W_temb,
                                           ei, etype, ntype, x, E);
    gemv_kernel<<<(N / 2 + 127) / 128, 128>>>(W_conv, batch_id, out, N);
}

// round 15
// speedup vs baseline: 1.0761x; 1.0428x over previous
#include <cuda_runtime.h>
#include <math.h>

// Problem constants (fixed by the dataset)
#define NB        8          // batch
#define C_IN      4
#define N_ETYPE   5
#define N_NTYPE   7
#define C_OUT     32
#define TEMB_CH   512
#define FAN       55         // N_ETYPE * (C_IN + N_NTYPE)
#define NMAX      400000

// Scatter accumulators (zero at load; gemv re-zeros what it consumes):
__device__ float    g_xsum[NMAX * N_ETYPE * 4];   // 32 MB
__device__ unsigned g_cnt [NMAX * N_ETYPE * 2];   // 16 MB
__device__ float    g_l2  [NB * TEMB_CH];         // lin2 pre-activation accum
__device__ float    g_inj [NB * C_OUT];
__device__ int      g_done0;                      // temb-block arrivals
__device__ int      g_done1;                      // inj-block arrivals

// ---------------------------------------------------------------------------
// MEGA kernel (R12-proven form), 512 threads/block:
//  blocks [0,64)   : temb lin1+lin2 partials -> g_l2 (atomicAdd), signal done0
//  blocks [64,72)  : spin on done0==64, then inj = swish(l2+b2) @ Wt -> g_inj,
//                    re-zero g_l2, self-reset counters for graph replay
//  blocks [72,...) : edge scatter, 2 edges/thread, direct x/ntype gather
// ---------------------------------------------------------------------------
__global__ void __launch_bounds__(512)
mega_kernel(const float* __restrict__ t,
            const float* __restrict__ W1,
            const float* __restrict__ b1,
            const float* __restrict__ W2,
            const float* __restrict__ b2,
            const float* __restrict__ Wt,
            const int* __restrict__ ei,
            const int* __restrict__ etype,
            const int* __restrict__ ntype,
            const float* __restrict__ x,
            int E) {
    const int tid = threadIdx.x;

    if (blockIdx.x < 64) {
        __shared__ float emb[NB][128];
        __shared__ float h1s[NB][64];
        const int ks = blockIdx.x >> 3;
        const int bo = blockIdx.x & 7;
        const int b  = tid >> 6;
        const int j  = tid & 63;

        {
            float f = expf(-(float)j * (logf(10000.0f) / 63.0f));
            float ang = t[b] * f;
            emb[b][j]      = sinf(ang);
            emb[b][j + 64] = cosf(ang);
        }
        __syncthreads();
        {
            float s = b1[ks * 64 + j];
            const float* w = W1 + ks * 64 + j;
            #pragma unroll 8
            for (int i = 0; i < 128; i++) s += emb[b][i] * w[(size_t)i * TEMB_CH];
            h1s[b][j] = s * (1.0f / (1.0f + expf(-s)));
        }
        __syncthreads();
        {
            float s = 0.0f;
            const float* w = W2 + (size_t)(ks * 64) * TEMB_CH + bo * 64 + j;
            #pragma unroll 8
            for (int k = 0; k < 64; k++) s += h1s[b][k] * w[(size_t)k * TEMB_CH];
            atomicAdd(g_l2 + b * TEMB_CH + bo * 64 + j, s);
        }
        __syncthreads();
        if (tid == 0) {
            __threadfence();
            atomicAdd(&g_done0, 1);
        }
        return;
    }

    if (blockIdx.x < 72) {
        __shared__ float sws[TEMB_CH];
        __shared__ float part[16][33];
        const int b = blockIdx.x - 64;

        if (tid == 0) {
            while (atomicAdd(&g_done0, 0) < 64) __nanosleep(200);
            __threadfence();
        }
        __syncthreads();

        for (int i = tid; i < TEMB_CH; i += 512) {
            float v = __ldcg(g_l2 + b * TEMB_CH + i) + b2[i];
            sws[i] = v * (1.0f / (1.0f + expf(-v)));
        }
        __syncthreads();
        for (int i = tid; i < TEMB_CH; i += 512)   // restore zero-invariant
            g_l2[b * TEMB_CH + i] = 0.0f;

        const int c  = tid & 31;
        const int ks = tid >> 5;                   // 0..15
        const float* sw = sws + ks * 32;
        const float* w  = Wt + (ks * 32) * C_OUT + c;
        float s = 0.0f;
        #pragma unroll 8
        for (int i = 0; i < 32; i++) s += sw[i] * w[i * C_OUT];
        part[ks][c] = s;
        __syncthreads();

        if (tid < 32) {
            float v = 0.0f;
            #pragma unroll
            for (int k = 0; k < 16; k++) v += part[k][tid];
            g_inj[b * C_OUT + tid] = v;
        }
        __syncthreads();
        if (tid == 0) {
            __threadfence();
            int r = atomicAdd(&g_done1, 1);
            if (r == 7) {
                atomicExch(&g_done0, 0);
                atomicExch(&g_done1, 0);
            }
        }
        return;
    }

    // ---- edge scatter: 2 edges per thread (default cache policy) ----
    int e2 = ((blockIdx.x - 72) * blockDim.x + tid) * 2;
    if (e2 >= E) return;
    int2 rows = *reinterpret_cast<const int2*>(ei + e2);
    int2 cols = *reinterpret_cast<const int2*>(ei + E + e2);
    int2 ets  = *reinterpret_cast<const int2*>(etype + e2);

    int nt0 = __ldg(ntype + cols.x);
    int nt1 = __ldg(ntype + cols.y);
    float4 xv0 = *reinterpret_cast<const float4*>(x + (size_t)cols.x * C_IN);
    float4 xv1 = *reinterpret_cast<const float4*>(x + (size_t)cols.y * C_IN);

    size_t bk0 = (size_t)rows.x * N_ETYPE + ets.x;
    size_t bk1 = (size_t)rows.y * N_ETYPE + ets.y;

    asm volatile("red.global.add.v4.f32 [%0], {%1,%2,%3,%4};"
                 :: "l"(g_xsum + bk0 * 4), "f"(xv0.x), "f"(xv0.y), "f"(xv0.z), "f"(xv0.w)
                 : "memory");
    asm volatile("red.global.add.v4.f32 [%0], {%1,%2,%3,%4};"
                 :: "l"(g_xsum + bk1 * 4), "f"(xv1.x), "f"(xv1.y), "f"(xv1.z), "f"(xv1.w)
                 : "memory");
    atomicAdd(g_cnt + bk0 * 2 + (nt0 >> 2), 1u << ((nt0 & 3) * 8));
    atomicAdd(g_cnt + bk1 * 2 + (nt1 >> 2), 1u << ((nt1 & 3) * 8));
}

// ---------------------------------------------------------------------------
// u8 counter -> exact fp32 via PRMT magic number.
// ---------------------------------------------------------------------------
template <int K>
__device__ __forceinline__ float byte2f(unsigned w) {
    unsigned r;
    asm("prmt.b32 %0, %1, %2, %3;"
        : "=r"(r) : "r"(w), "r"(0x4B000000u), "n"(0x7540u | K));
    return __uint_as_float(r) - 8388608.0f;
}

// ---------------------------------------------------------------------------
// GEMV v10: 4 nodes x 8 channels per thread (4-way channel split).
// Warp-level LDS/node stays 3.44 (same as v9: it depends only on nodes/thread)
// but the accumulator footprint halves (16 u64 vs 32) -> more blocks/SM, more
// latency hiding. Quarter h reads Ws[... + h*8] (32B offsets: conflict-free).
// ---------------------------------------------------------------------------
__global__ void __launch_bounds__(128, 4)
gemv_kernel(const float* __restrict__ Wc,
            const int* __restrict__ batch_id,
            float* __restrict__ out,
            int N) {
    __shared__ __align__(16) float Ws[FAN * C_OUT];   // pre-scaled by 0.2
    __shared__ float injs[NB * 33];
    const int tid = threadIdx.x;
    for (int i = tid; i < FAN * C_OUT; i += blockDim.x) Ws[i] = Wc[i] * 0.2f;
    for (int i = tid; i < NB * C_OUT; i += blockDim.x) {
        int b = i >> 5, c = i & 31;
        injs[b * 33 + c] = g_inj[i];
    }
    __syncthreads();

    const int gid  = blockIdx.x * blockDim.x + tid;
    const int h    = gid & 3;                 // channel quarter: [h*8, h*8+8)
    const int base = (gid >> 2) * 4;          // this group's 4 nodes
    if (base >= N) return;

    unsigned long long acc[4][4];             // 4 nodes x 8 channels (4 u64)
    #pragma unroll
    for (int nd = 0; nd < 4; nd++)
        #pragma unroll
        for (int k = 0; k < 4; k++) acc[nd][k] = 0ULL;

    float*    xp = g_xsum + (size_t)base * (N_ETYPE * 4);   // 16B aligned
    unsigned* cp = g_cnt  + (size_t)base * (N_ETYPE * 2);   // 16B aligned (base%4==0)

    #pragma unroll
    for (int et = 0; et < N_ETYPE; et++) {
        float a[4][11];
        #pragma unroll
        for (int nd = 0; nd < 4; nd++) {
            float4 v = *reinterpret_cast<float4*>(xp + nd * (N_ETYPE * 4) + et * 4);
            uint2  c = *reinterpret_cast<uint2*>(cp + nd * (N_ETYPE * 2) + et * 2);
            a[nd][0] = v.x; a[nd][1] = v.y; a[nd][2] = v.z; a[nd][3] = v.w;
            a[nd][4] = byte2f<0>(c.x); a[nd][5] = byte2f<1>(c.x);
            a[nd][6] = byte2f<2>(c.x); a[nd][7] = byte2f<3>(c.x);
            a[nd][8] = byte2f<0>(c.y); a[nd][9] = byte2f<1>(c.y);
            a[nd][10] = byte2f<2>(c.y);
        }

        #pragma unroll
        for (int j = 0; j < 11; j++) {
            const ulonglong2* Wv =
                reinterpret_cast<const ulonglong2*>(&Ws[(et * 11 + j) * C_OUT + h * 8]);
            ulonglong2 w0 = Wv[0];             // channels [h*8, h*8+4)
            ulonglong2 w1 = Wv[1];             // channels [h*8+4, h*8+8)
            #pragma unroll
            for (int nd = 0; nd < 4; nd++) {
                unsigned long long av;
                asm("mov.b64 %0, {%1, %1};" : "=l"(av) : "f"(a[nd][j]));
                asm("fma.rn.f32x2 %0, %1, %2, %0;" : "+l"(acc[nd][0]) : "l"(av), "l"(w0.x));
                asm("fma.rn.f32x2 %0, %1, %2, %0;" : "+l"(acc[nd][1]) : "l"(av), "l"(w0.y));
                asm("fma.rn.f32x2 %0, %1, %2, %0;" : "+l"(acc[nd][2]) : "l"(av), "l"(w1.x));
                asm("fma.rn.f32x2 %0, %1, %2, %0;" : "+l"(acc[nd][3]) : "l"(av), "l"(w1.y));
            }
        }
    }

    int4 bb = *reinterpret_cast<const int4*>(batch_id + base);
    const int bbl[4] = {bb.x, bb.y, bb.z, bb.w};
    #pragma unroll
    for (int nd = 0; nd < 4; nd++) {
        const float* iv = &injs[bbl[nd] * 33 + h * 8];
        float* op = out + (size_t)(base + nd) * C_OUT + h * 8;
        float l0, h0, l1, h1;
        asm("mov.b64 {%0, %1}, %2;" : "=f"(l0), "=f"(h0) : "l"(acc[nd][0]));
        asm("mov.b64 {%0, %1}, %2;" : "=f"(l1), "=f"(h1) : "l"(acc[nd][1]));
        float4 o;
        o.x = l0 + iv[0]; o.y = h0 + iv[1];
        o.z = l1 + iv[2]; o.w = h1 + iv[3];
        *reinterpret_cast<float4*>(op) = o;
        asm("mov.b64 {%0, %1}, %2;" : "=f"(l0), "=f"(h0) : "l"(acc[nd][2]));
        asm("mov.b64 {%0, %1}, %2;" : "=f"(l1), "=f"(h1) : "l"(acc[nd][3]));
        float4 p;
        p.x = l0 + iv[4]; p.y = h0 + iv[5];
        p.z = l1 + iv[6]; p.w = h1 + iv[7];
        *reinterpret_cast<float4*>(op + 4) = p;
    }

    // Re-zero: quarter h clears node base+h entirely (no overlap).
    {
        float*    zxp = xp + h * (N_ETYPE * 4);   // node h: 80B, 16B aligned
        unsigned* zcp = cp + h * (N_ETYPE * 2);   // node h: 40B, 8B aligned
        float4 z4 = make_float4(0.f, 0.f, 0.f, 0.f);
        #pragma unroll
        for (int i = 0; i < N_ETYPE; i++)
            *reinterpret_cast<float4*>(zxp + i * 4) = z4;
        uint2 z2 = make_uint2(0u, 0u);
        #pragma unroll
        for (int i = 0; i < N_ETYPE; i++)
            *reinterpret_cast<uint2*>(zcp + i * 2) = z2;
    }
}

// ---------------------------------------------------------------------------
// Inputs (metadata order):
//  0 x [N,4] f32        1 t [8] f32          2 edge_index [2,E] i32
//  3 edge_type [E] i32  4 node_type [N] i32  5 batch_id [N] i32
//  6 W_conv [55,32] f32 7 W1 [128,512]       8 b1 [512]
//  9 W2 [512,512]      10 b2 [512]          11 W_temb [512,32]
// Output: [N,32] f32
// ---------------------------------------------------------------------------
extern "C" void kernel_launch(void* const* d_in, const int* in_sizes, int n_in,
                              void* d_out, int out_size) {
    const float* x        = (const float*)d_in[0];
    const float* t        = (const float*)d_in[1];
    const int*   ei       = (const int*)d_in[2];
    const int*   etype    = (const int*)d_in[3];
    const int*   ntype    = (const int*)d_in[4];
    const int*   batch_id = (const int*)d_in[5];
    const float* W_conv   = (const float*)d_in[6];
    const float* W1       = (const float*)d_in[7];
    const float* b1       = (const float*)d_in[8];
    const float* W2       = (const float*)d_in[9];
    const float* b2       = (const float*)d_in[10];
    const float* W_temb   = (const float*)d_in[11];
    float* out = (float*)d_out;

    const int E = in_sizes[3];
    const int N = in_sizes[4];
    const int edge_blocks = (E / 2 + 511) / 512;

    mega_kernel<<<72 + edge_blocks, 512>>>(t, W1, b1, W2, b2, W_temb,
                                           ei, etype, ntype, x, E);
    gemv_kernel<<<(N + 127) / 128, 128>>>(W_conv, batch_id, out, N);
}

// round 16
// speedup vs baseline: 1.0811x; 1.0046x over previous
#include <cuda_runtime.h>
#include <math.h>

// Problem constants (fixed by the dataset)
#define NB        8          // batch
#define C_IN      4
#define N_ETYPE   5
#define N_NTYPE   7
#define C_OUT     32
#define TEMB_CH   512
#define FAN       55         // N_ETYPE * (C_IN + N_NTYPE)
#define NMAX      400000

// Scatter accumulators (zero at load; gemv re-zeros what it consumes):
__device__ float    g_xsum[NMAX * N_ETYPE * 4];   // 32 MB
__device__ unsigned g_cnt [NMAX * N_ETYPE * 2];   // 16 MB
__device__ float    g_l2  [NB * TEMB_CH];         // lin2 pre-activation accum
__device__ float    g_inj [NB * C_OUT];
__device__ int      g_done0;                      // temb-block arrivals
__device__ int      g_done1;                      // inj-block arrivals

// ---------------------------------------------------------------------------
// MEGA kernel (R12-proven form), 512 threads/block:
//  blocks [0,64)   : temb lin1+lin2 partials -> g_l2 (atomicAdd), signal done0
//  blocks [64,72)  : spin on done0==64, then inj = swish(l2+b2) @ Wt -> g_inj,
//                    re-zero g_l2, self-reset counters for graph replay
//  blocks [72,...) : edge scatter, 2 edges/thread, direct x/ntype gather
// ---------------------------------------------------------------------------
__global__ void __launch_bounds__(512)
mega_kernel(const float* __restrict__ t,
            const float* __restrict__ W1,
            const float* __restrict__ b1,
            const float* __restrict__ W2,
            const float* __restrict__ b2,
            const float* __restrict__ Wt,
            const int* __restrict__ ei,
            const int* __restrict__ etype,
            const int* __restrict__ ntype,
            const float* __restrict__ x,
            int E) {
    const int tid = threadIdx.x;

    if (blockIdx.x < 64) {
        __shared__ float emb[NB][128];
        __shared__ float h1s[NB][64];
        const int ks = blockIdx.x >> 3;
        const int bo = blockIdx.x & 7;
        const int b  = tid >> 6;
        const int j  = tid & 63;

        {
            float f = expf(-(float)j * (logf(10000.0f) / 63.0f));
            float ang = t[b] * f;
            emb[b][j]      = sinf(ang);
            emb[b][j + 64] = cosf(ang);
        }
        __syncthreads();
        {
            float s = b1[ks * 64 + j];
            const float* w = W1 + ks * 64 + j;
            #pragma unroll 8
            for (int i = 0; i < 128; i++) s += emb[b][i] * w[(size_t)i * TEMB_CH];
            h1s[b][j] = s * (1.0f / (1.0f + expf(-s)));
        }
        __syncthreads();
        {
            float s = 0.0f;
            const float* w = W2 + (size_t)(ks * 64) * TEMB_CH + bo * 64 + j;
            #pragma unroll 8
            for (int k = 0; k < 64; k++) s += h1s[b][k] * w[(size_t)k * TEMB_CH];
            atomicAdd(g_l2 + b * TEMB_CH + bo * 64 + j, s);
        }
        __syncthreads();
        if (tid == 0) {
            __threadfence();
            atomicAdd(&g_done0, 1);
        }
        return;
    }

    if (blockIdx.x < 72) {
        __shared__ float sws[TEMB_CH];
        __shared__ float part[16][33];
        const int b = blockIdx.x - 64;

        if (tid == 0) {
            while (atomicAdd(&g_done0, 0) < 64) __nanosleep(200);
            __threadfence();
        }
        __syncthreads();

        for (int i = tid; i < TEMB_CH; i += 512) {
            float v = __ldcg(g_l2 + b * TEMB_CH + i) + b2[i];
            sws[i] = v * (1.0f / (1.0f + expf(-v)));
        }
        __syncthreads();
        for (int i = tid; i < TEMB_CH; i += 512)   // restore zero-invariant
            g_l2[b * TEMB_CH + i] = 0.0f;

        const int c  = tid & 31;
        const int ks = tid >> 5;                   // 0..15
        const float* sw = sws + ks * 32;
        const float* w  = Wt + (ks * 32) * C_OUT + c;
        float s = 0.0f;
        #pragma unroll 8
        for (int i = 0; i < 32; i++) s += sw[i] * w[i * C_OUT];
        part[ks][c] = s;
        __syncthreads();

        if (tid < 32) {
            float v = 0.0f;
            #pragma unroll
            for (int k = 0; k < 16; k++) v += part[k][tid];
            g_inj[b * C_OUT + tid] = v;
        }
        __syncthreads();
        if (tid == 0) {
            __threadfence();
            int r = atomicAdd(&g_done1, 1);
            if (r == 7) {
                atomicExch(&g_done0, 0);
                atomicExch(&g_done1, 0);
            }
        }
        return;
    }

    // ---- edge scatter: 2 edges per thread (default cache policy) ----
    int e2 = ((blockIdx.x - 72) * blockDim.x + tid) * 2;
    if (e2 >= E) return;
    int2 rows = *reinterpret_cast<const int2*>(ei + e2);
    int2 cols = *reinterpret_cast<const int2*>(ei + E + e2);
    int2 ets  = *reinterpret_cast<const int2*>(etype + e2);

    int nt0 = __ldg(ntype + cols.x);
    int nt1 = __ldg(ntype + cols.y);
    float4 xv0 = *reinterpret_cast<const float4*>(x + (size_t)cols.x * C_IN);
    float4 xv1 = *reinterpret_cast<const float4*>(x + (size_t)cols.y * C_IN);

    size_t bk0 = (size_t)rows.x * N_ETYPE + ets.x;
    size_t bk1 = (size_t)rows.y * N_ETYPE + ets.y;

    asm volatile("red.global.add.v4.f32 [%0], {%1,%2,%3,%4};"
                 :: "l"(g_xsum + bk0 * 4), "f"(xv0.x), "f"(xv0.y), "f"(xv0.z), "f"(xv0.w)
                 : "memory");
    asm volatile("red.global.add.v4.f32 [%0], {%1,%2,%3,%4};"
                 :: "l"(g_xsum + bk1 * 4), "f"(xv1.x), "f"(xv1.y), "f"(xv1.z), "f"(xv1.w)
                 : "memory");
    atomicAdd(g_cnt + bk0 * 2 + (nt0 >> 2), 1u << ((nt0 & 3) * 8));
    atomicAdd(g_cnt + bk1 * 2 + (nt1 >> 2), 1u << ((nt1 & 3) * 8));
}

// ---------------------------------------------------------------------------
// u8 counter -> exact fp32 via PRMT magic number.
// ---------------------------------------------------------------------------
template <int K>
__device__ __forceinline__ float byte2f(unsigned w) {
    unsigned r;
    asm("prmt.b32 %0, %1, %2, %3;"
        : "=r"(r) : "r"(w), "r"(0x4B000000u), "n"(0x7540u | K));
    return __uint_as_float(r) - 8388608.0f;
}

// Select a[j] for bucket data (v: x-sums, c: packed u8 counts) at the single
// point of use -- no staging array, minimal live registers. j is compile-time.
template <int J>
__device__ __forceinline__ float aval(const float4& v, const uint2& c) {
    if      (J == 0) return v.x;
    else if (J == 1) return v.y;
    else if (J == 2) return v.z;
    else if (J == 3) return v.w;
    else if (J == 4) return byte2f<0>(c.x);
    else if (J == 5) return byte2f<1>(c.x);
    else if (J == 6) return byte2f<2>(c.x);
    else if (J == 7) return byte2f<3>(c.x);
    else if (J == 8) return byte2f<0>(c.y);
    else if (J == 9) return byte2f<1>(c.y);
    else             return byte2f<2>(c.y);
}

// ---------------------------------------------------------------------------
// GEMV v11: 4 nodes x 8 channels per thread (4-way channel split), count
// conversion INLINED at point of use (each a[j] is consumed exactly once per
// et, so staging bought no reuse -- only ~44 live registers). Target 5
// blocks/SM (20 warps) for latency hiding at the same 3.44 warp-LDS/node.
// ---------------------------------------------------------------------------
template <int ET, int J>
struct JLoop {
    __device__ __forceinline__ static void run(
        const float* Ws, int h, const float4* v, const uint2* c,
        unsigned long long acc[4][4]) {
        const ulonglong2* Wv =
            reinterpret_cast<const ulonglong2*>(Ws + (ET * 11 + J) * C_OUT + h * 8);
        ulonglong2 w0 = Wv[0];
        ulonglong2 w1 = Wv[1];
        #pragma unroll
        for (int nd = 0; nd < 4; nd++) {
            float a = aval<J>(v[nd], c[nd]);
            unsigned long long av;
            asm("mov.b64 %0, {%1, %1};" : "=l"(av) : "f"(a));
            asm("fma.rn.f32x2 %0, %1, %2, %0;" : "+l"(acc[nd][0]) : "l"(av), "l"(w0.x));
            asm("fma.rn.f32x2 %0, %1, %2, %0;" : "+l"(acc[nd][1]) : "l"(av), "l"(w0.y));
            asm("fma.rn.f32x2 %0, %1, %2, %0;" : "+l"(acc[nd][2]) : "l"(av), "l"(w1.x));
            asm("fma.rn.f32x2 %0, %1, %2, %0;" : "+l"(acc[nd][3]) : "l"(av), "l"(w1.y));
        }
        JLoop<ET, J + 1>::run(Ws, h, v, c, acc);
    }
};
template <int ET>
struct JLoop<ET, 11> {
    __device__ __forceinline__ static void run(
        const float*, int, const float4*, const uint2*, unsigned long long[4][4]) {}
};

__global__ void __launch_bounds__(128, 5)
gemv_kernel(const float* __restrict__ Wc,
            const int* __restrict__ batch_id,
            float* __restrict__ out,
            int N) {
    __shared__ __align__(16) float Ws[FAN * C_OUT];   // pre-scaled by 0.2
    __shared__ float injs[NB * 33];
    const int tid = threadIdx.x;
    for (int i = tid; i < FAN * C_OUT; i += blockDim.x) Ws[i] = Wc[i] * 0.2f;
    for (int i = tid; i < NB * C_OUT; i += blockDim.x) {
        int b = i >> 5, c = i & 31;
        injs[b * 33 + c] = g_inj[i];
    }
    __syncthreads();

    const int gid  = blockIdx.x * blockDim.x + tid;
    const int h    = gid & 3;                 // channel quarter: [h*8, h*8+8)
    const int base = (gid >> 2) * 4;          // this group's 4 nodes
    if (base >= N) return;

    unsigned long long acc[4][4];             // 4 nodes x 8 channels (4 u64)
    #pragma unroll
    for (int nd = 0; nd < 4; nd++)
        #pragma unroll
        for (int k = 0; k < 4; k++) acc[nd][k] = 0ULL;

    float*    xp = g_xsum + (size_t)base * (N_ETYPE * 4);   // 16B aligned
    unsigned* cp = g_cnt  + (size_t)base * (N_ETYPE * 2);   // 16B aligned (base%4==0)

    #pragma unroll
    for (int et = 0; et < N_ETYPE; et++) {
        float4 v[4];
        uint2  c[4];
        #pragma unroll
        for (int nd = 0; nd < 4; nd++) {
            v[nd] = *reinterpret_cast<float4*>(xp + nd * (N_ETYPE * 4) + et * 4);
            c[nd] = *reinterpret_cast<uint2*>(cp + nd * (N_ETYPE * 2) + et * 2);
        }
        switch (et) {
            case 0: JLoop<0, 0>::run(Ws, h, v, c, acc); break;
            case 1: JLoop<1, 0>::run(Ws, h, v, c, acc); break;
            case 2: JLoop<2, 0>::run(Ws, h, v, c, acc); break;
            case 3: JLoop<3, 0>::run(Ws, h, v, c, acc); break;
            case 4: JLoop<4, 0>::run(Ws, h, v, c, acc); break;
        }
    }

    int4 bb = *reinterpret_cast<const int4*>(batch_id + base);
    const int bbl[4] = {bb.x, bb.y, bb.z, bb.w};
    #pragma unroll
    for (int nd = 0; nd < 4; nd++) {
        const float* iv = &injs[bbl[nd] * 33 + h * 8];
        float* op = out + (size_t)(base + nd) * C_OUT + h * 8;
        float l0, h0, l1, h1;
        asm("mov.b64 {%0, %1}, %2;" : "=f"(l0), "=f"(h0) : "l"(acc[nd][0]));
        asm("mov.b64 {%0, %1}, %2;" : "=f"(l1), "=f"(h1) : "l"(acc[nd][1]));
        float4 o;
        o.x = l0 + iv[0]; o.y = h0 + iv[1];
        o.z = l1 + iv[2]; o.w = h1 + iv[3];
        *reinterpret_cast<float4*>(op) = o;
        asm("mov.b64 {%0, %1}, %2;" : "=f"(l0), "=f"(h0) : "l"(acc[nd][2]));
        asm("mov.b64 {%0, %1}, %2;" : "=f"(l1), "=f"(h1) : "l"(acc[nd][3]));
        float4 p;
        p.x = l0 + iv[4]; p.y = h0 + iv[5];
        p.z = l1 + iv[6]; p.w = h1 + iv[7];
        *reinterpret_cast<float4*>(op + 4) = p;
    }

    // Re-zero: quarter h clears node base+h entirely (no overlap).
    {
        float*    zxp = xp + h * (N_ETYPE * 4);   // node h: 80B, 16B aligned
        unsigned* zcp = cp + h * (N_ETYPE * 2);   // node h: 40B, 8B aligned
        float4 z4 = make_float4(0.f, 0.f, 0.f, 0.f);
        #pragma unroll
        for (int i = 0; i < N_ETYPE; i++)
            *reinterpret_cast<float4*>(zxp + i * 4) = z4;
        uint2 z2 = make_uint2(0u, 0u);
        #pragma unroll
        for (int i = 0; i < N_ETYPE; i++)
            *reinterpret_cast<uint2*>(zcp + i * 2) = z2;
    }
}

// ---------------------------------------------------------------------------
// Inputs (metadata order):
//  0 x [N,4] f32        1 t [8] f32          2 edge_index [2,E] i32
//  3 edge_type [E] i32  4 node_type [N] i32  5 batch_id [N] i32
//  6 W_conv [55,32] f32 7 W1 [128,512]       8 b1 [512]
//  9 W2 [512,512]      10 b2 [512]          11 W_temb [512,32]
// Output: [N,32] f32
// ---------------------------------------------------------------------------
extern "C" void kernel_launch(void* const* d_in, const int* in_sizes, int n_in,
                              void* d_out, int out_size) {
    const float* x        = (const float*)d_in[0];
    const float* t        = (const float*)d_in[1];
    const int*   ei       = (const int*)d_in[2];
    const int*   etype    = (const int*)d_in[3];
    const int*   ntype    = (const int*)d_in[4];
    const int*   batch_id = (const int*)d_in[5];
    const float* W_conv   = (const float*)d_in[6];
    const float* W1       = (const float*)d_in[7];
    const float* b1       = (const float*)d_in[8];
    const float* W2       = (const float*)d_in[9];
    const float* b2       = (const float*)d_in[10];
    const float* W_temb   = (const float*)d_in[11];
    float* out = (float*)d_out;

    const int E = in_sizes[3];
    const int N = in_sizes[4];
    const int edge_blocks = (E / 2 + 511) / 512;

    mega_kernel<<<72 + edge_blocks, 512>>>(t, W1, b1, W2, b2, W_temb,
                                           ei, etype, ntype, x, E);
    gemv_kernel<<<(N + 127) / 128, 128>>>(W_conv, batch_id, out, N);
}